// round 1
// baseline (speedup 1.0000x reference)
#include <cuda_runtime.h>
#include <math.h>

#define HDIM 128
#define MAXN 200000

// Mailbox scratch (segment sums). Written fully by gather_kernel each call.
__device__ float g_mh1[MAXN * HDIM];
__device__ float g_mc1[MAXN * HDIM];
__device__ float g_mh2[MAXN * HDIM];
__device__ float g_mc2[MAXN * HDIM];

// One warp per node. dst is sorted, so the node's edges are a contiguous
// range found by binary search; sum child rows in registers, single store.
__global__ void gather_kernel(const float* __restrict__ h1, const float* __restrict__ c1,
                              const float* __restrict__ h2, const float* __restrict__ c2,
                              const int* __restrict__ src, const int* __restrict__ dst,
                              int n, int e)
{
    int node = (blockIdx.x * blockDim.x + threadIdx.x) >> 5;
    int lane = threadIdx.x & 31;
    if (node >= n) return;

    int lo = 0, hi = e;
    while (lo < hi) { int mid = (lo + hi) >> 1; if (dst[mid] < node) lo = mid + 1; else hi = mid; }
    int s = lo;
    hi = e;
    while (lo < hi) { int mid = (lo + hi) >> 1; if (dst[mid] < node + 1) lo = mid + 1; else hi = mid; }
    int send = lo;

    float4 a1 = make_float4(0.f, 0.f, 0.f, 0.f);
    float4 a2 = a1, a3 = a1, a4 = a1;
    int col = lane * 4;

    for (int idx = s; idx < send; ++idx) {
        int b = src[idx] * HDIM + col;
        float4 v;
        v = *(const float4*)(h1 + b); a1.x += v.x; a1.y += v.y; a1.z += v.z; a1.w += v.w;
        v = *(const float4*)(c1 + b); a2.x += v.x; a2.y += v.y; a2.z += v.z; a2.w += v.w;
        v = *(const float4*)(h2 + b); a3.x += v.x; a3.y += v.y; a3.z += v.z; a3.w += v.w;
        v = *(const float4*)(c2 + b); a4.x += v.x; a4.y += v.y; a4.z += v.z; a4.w += v.w;
    }

    int ob = node * HDIM + col;
    *(float4*)(g_mh1 + ob) = a1;
    *(float4*)(g_mc1 + ob) = a2;
    *(float4*)(g_mh2 + ob) = a3;
    *(float4*)(g_mc2 + ob) = a4;
}

// Fused GEMM + gates.
// Computes G[m, col] = sum_k A1[m,k]*W[k,col] + sum_k A2[m,k]*U[k,col] + bW[col] + bU[col]
// for a 128-row x (4 gates x 32 h) tile, then applies the LSTM gating with mc,
// writing c_out and h_out. A2/mc are the device-global mailboxes (phase-selected).
// Tile: BM=128 rows, tile-cols = 128 (gate-major: col = g*32 + hh, h = h0 + hh),
// BK=16, 256 threads, 8x8 per-thread accumulators.
__global__ __launch_bounds__(256) void lstm_gemm_kernel(
    const float* __restrict__ A1,
    const float* __restrict__ W, const float* __restrict__ U,
    const float* __restrict__ bW, const float* __restrict__ bU,
    float* __restrict__ h_out, float* __restrict__ c_out,
    int nrows, int phase)
{
    extern __shared__ float smem[];
    float* As = smem;          // [16][128]
    float* Bs = smem + 2048;   // [16][128]
    float* Es = smem;          // [128][128] epilogue reuse (64KB)

    const float* A2 = (phase == 0) ? g_mh1 : g_mh2;
    const float* mc = (phase == 0) ? g_mc1 : g_mc2;

    const int row0 = blockIdx.x * 128;
    const int h0   = blockIdx.y * 32;
    const int tid  = threadIdx.x;
    const int tx   = tid & 15;
    const int ty   = tid >> 4;

    float acc[8][8];
#pragma unroll
    for (int i = 0; i < 8; ++i)
#pragma unroll
        for (int j = 0; j < 8; ++j) acc[i][j] = 0.f;

    for (int kt = 0; kt < 16; ++kt) {
        int k0 = kt * 16;
        const float* Aptr; const float* Bptr; int kk;
        if (k0 < 128) { Aptr = A1; Bptr = W; kk = k0; }
        else          { Aptr = A2; Bptr = U; kk = k0 - 128; }

        // A tile: 128 rows x 16 k, loaded as float4 along k, stored transposed As[k][m]
        {
            int i0 = tid, i1 = tid + 256;
            {
                int m = i0 >> 2, kq = i0 & 3;
                int r = row0 + m;
                float4 v = (r < nrows) ? *(const float4*)(Aptr + (size_t)r * 128 + kk + kq * 4)
                                       : make_float4(0.f, 0.f, 0.f, 0.f);
                As[(kq * 4 + 0) * 128 + m] = v.x;
                As[(kq * 4 + 1) * 128 + m] = v.y;
                As[(kq * 4 + 2) * 128 + m] = v.z;
                As[(kq * 4 + 3) * 128 + m] = v.w;
            }
            {
                int m = i1 >> 2, kq = i1 & 3;
                int r = row0 + m;
                float4 v = (r < nrows) ? *(const float4*)(Aptr + (size_t)r * 128 + kk + kq * 4)
                                       : make_float4(0.f, 0.f, 0.f, 0.f);
                As[(kq * 4 + 0) * 128 + m] = v.x;
                As[(kq * 4 + 1) * 128 + m] = v.y;
                As[(kq * 4 + 2) * 128 + m] = v.z;
                As[(kq * 4 + 3) * 128 + m] = v.w;
            }
        }
        // B tile: 16 k x 128 cols (col = g*32+hh maps to weight col g*128+h0+hh)
        {
#pragma unroll
            for (int ii = 0; ii < 2; ++ii) {
                int i = tid + ii * 256;
                int kr = i >> 5, q = i & 31;
                int c4 = q * 4;
                int g = c4 >> 5, hh = c4 & 31;
                float4 v = *(const float4*)(Bptr + (size_t)(kk + kr) * 512 + g * 128 + h0 + hh);
                *(float4*)(Bs + kr * 128 + c4) = v;
            }
        }
        __syncthreads();

#pragma unroll
        for (int k = 0; k < 16; ++k) {
            float a[8], b[8];
            *(float4*)(&a[0]) = *(const float4*)(As + k * 128 + ty * 8);
            *(float4*)(&a[4]) = *(const float4*)(As + k * 128 + ty * 8 + 4);
            *(float4*)(&b[0]) = *(const float4*)(Bs + k * 128 + tx * 8);
            *(float4*)(&b[4]) = *(const float4*)(Bs + k * 128 + tx * 8 + 4);
#pragma unroll
            for (int mi = 0; mi < 8; ++mi)
#pragma unroll
                for (int ni = 0; ni < 8; ++ni)
                    acc[mi][ni] += a[mi] * b[ni];
        }
        __syncthreads();
    }

    // Bias per column, then park the tile in smem for the gate exchange.
    float bias[8];
#pragma unroll
    for (int ni = 0; ni < 8; ++ni) {
        int c = tx * 8 + ni;
        int g = c >> 5, hh = c & 31;
        int gc = g * 128 + h0 + hh;
        bias[ni] = bW[gc] + bU[gc];
    }
#pragma unroll
    for (int mi = 0; mi < 8; ++mi) {
#pragma unroll
        for (int ni = 0; ni < 8; ni += 4) {
            float4 v;
            v.x = acc[mi][ni + 0] + bias[ni + 0];
            v.y = acc[mi][ni + 1] + bias[ni + 1];
            v.z = acc[mi][ni + 2] + bias[ni + 2];
            v.w = acc[mi][ni + 3] + bias[ni + 3];
            *(float4*)(Es + (ty * 8 + mi) * 128 + tx * 8 + ni) = v;
        }
    }
    __syncthreads();

    // Gate pass: thread -> (hh = tid&31, rows tid>>5 + 8*it). Conflict-free LDS,
    // coalesced 128B stores.
    int hh = tid & 31;
    int rbase = tid >> 5;
    for (int it = 0; it < 16; ++it) {
        int r = rbase + it * 8;
        int grow = row0 + r;
        if (grow >= nrows) continue;
        float xi = Es[r * 128 + hh];
        float xo = Es[r * 128 + 32 + hh];
        float xu = Es[r * 128 + 64 + hh];
        float xf = Es[r * 128 + 96 + hh];
        float gi = 1.f / (1.f + __expf(-xi));
        float go = 1.f / (1.f + __expf(-xo));
        float gu = tanhf(xu);
        float gf = 1.f / (1.f + __expf(-xf));
        float mcv = mc[(size_t)grow * 128 + h0 + hh];
        float cn = gi * gu + gf * mcv;
        float hn = go * tanhf(cn);
        c_out[(size_t)grow * 128 + h0 + hh] = cn;
        h_out[(size_t)grow * 128 + h0 + hh] = hn;
    }
}

extern "C" void kernel_launch(void* const* d_in, const int* in_sizes, int n_in,
                              void* d_out, int out_size)
{
    const float* x   = (const float*)d_in[0];
    const float* h1  = (const float*)d_in[1];
    const float* c1  = (const float*)d_in[2];
    const float* h2  = (const float*)d_in[3];
    const float* c2  = (const float*)d_in[4];
    const float* W1  = (const float*)d_in[5];
    const float* bW1 = (const float*)d_in[6];
    const float* U1  = (const float*)d_in[7];
    const float* bU1 = (const float*)d_in[8];
    const float* W2  = (const float*)d_in[9];
    const float* bW2 = (const float*)d_in[10];
    const float* U2  = (const float*)d_in[11];
    const float* bU2 = (const float*)d_in[12];
    const int*   src = (const int*)d_in[13];
    const int*   dst = (const int*)d_in[14];

    int n = in_sizes[1] / HDIM;
    int e = in_sizes[13];

    float* out = (float*)d_out;
    float* h1n = out;
    float* c1n = out + (size_t)n * HDIM;
    float* h2n = out + 2 * (size_t)n * HDIM;
    float* c2n = out + 3 * (size_t)n * HDIM;

    cudaFuncSetAttribute(lstm_gemm_kernel, cudaFuncAttributeMaxDynamicSharedMemorySize, 65536);

    // 1) mailbox segment sums (1 warp / node)
    {
        int blocks = (n + 7) / 8;   // 8 warps per 256-thread block
        gather_kernel<<<blocks, 256>>>(h1, c1, h2, c2, src, dst, n, e);
    }

    // 2) first gated update: [x | mh1] @ [W1; U1] + gates -> h1n, c1n
    {
        dim3 grid((n + 127) / 128, 4);
        lstm_gemm_kernel<<<grid, 256, 65536>>>(x, W1, U1, bW1, bU1, h1n, c1n, n, 0);
    }

    // 3) second gated update: [c1n | mh2] @ [W2; U2] + gates -> h2n, c2n
    {
        dim3 grid((n + 127) / 128, 4);
        lstm_gemm_kernel<<<grid, 256, 65536>>>(c1n, W2, U2, bW2, bU2, h2n, c2n, n, 1);
    }
}

// round 3
// speedup vs baseline: 1.5376x; 1.5376x over previous
#include <cuda_runtime.h>
#include <cstdint>
#include <math.h>

#define HDIM 128
#define MAXN 200000

// ---------------- device scratch ----------------
__device__ float g_mh1[MAXN * HDIM];
__device__ float g_mc1[MAXN * HDIM];
__device__ float g_mh2[MAXN * HDIM];
__device__ float g_mc2[MAXN * HDIM];
// transposed + tf32-rounded weights: [phase][n=512][k=256]
__device__ uint32_t g_Bt[2 * 512 * 256];

__device__ __forceinline__ uint32_t smem_u32(const void* p) {
    uint32_t a;
    asm("{ .reg .u64 t; cvta.to.shared.u64 t, %1; cvt.u32.u64 %0, t; }" : "=r"(a) : "l"(p));
    return a;
}
__device__ __forceinline__ uint32_t f2tf32(float f) {
    uint32_t o;
    asm("cvt.rna.tf32.f32 %0, %1;" : "=r"(o) : "f"(f));
    return o;
}
__device__ __forceinline__ void cp_async16(uint32_t dst, const void* src, int src_bytes) {
    asm volatile("cp.async.cg.shared.global [%0], [%1], 16, %2;"
                 :: "r"(dst), "l"(src), "r"(src_bytes) : "memory");
}
__device__ __forceinline__ void cp_commit() {
    asm volatile("cp.async.commit_group;" ::: "memory");
}
__device__ __forceinline__ void cp_wait1() {
    asm volatile("cp.async.wait_group 1;" ::: "memory");
}
__device__ __forceinline__ void cp_wait0() {
    asm volatile("cp.async.wait_group 0;" ::: "memory");
}
__device__ __forceinline__ void mma_tf32(float* d, uint32_t a0, uint32_t a1, uint32_t a2,
                                         uint32_t a3, uint32_t b0, uint32_t b1) {
    asm volatile(
        "mma.sync.aligned.m16n8k8.row.col.f32.tf32.tf32.f32 "
        "{%0,%1,%2,%3}, {%4,%5,%6,%7}, {%8,%9}, {%0,%1,%2,%3};"
        : "+f"(d[0]), "+f"(d[1]), "+f"(d[2]), "+f"(d[3])
        : "r"(a0), "r"(a1), "r"(a2), "r"(a3), "r"(b0), "r"(b1));
}

// XOR-swizzled smem offset for 128x32-float tiles (float index)
__device__ __forceinline__ int soff(int r, int kk) {
    return r * 32 + (((kk >> 2) ^ (r & 7)) << 2) + (kk & 3);
}

// ---------------- gather: sorted-dst segment sum, 1 warp / node ----------------
__global__ void gather_kernel(const float* __restrict__ h1, const float* __restrict__ c1,
                              const float* __restrict__ h2, const float* __restrict__ c2,
                              const int* __restrict__ src, const int* __restrict__ dst,
                              int n, int e)
{
    int node = (blockIdx.x * blockDim.x + threadIdx.x) >> 5;
    int lane = threadIdx.x & 31;
    if (node >= n) return;

    int lo = 0, hi = e;
    while (lo < hi) { int mid = (lo + hi) >> 1; if (dst[mid] < node) lo = mid + 1; else hi = mid; }
    int s = lo;
    hi = e;
    while (lo < hi) { int mid = (lo + hi) >> 1; if (dst[mid] < node + 1) lo = mid + 1; else hi = mid; }
    int send = lo;

    float4 a1 = make_float4(0.f, 0.f, 0.f, 0.f);
    float4 a2 = a1, a3 = a1, a4 = a1;
    int col = lane * 4;

    for (int idx = s; idx < send; ++idx) {
        int b = src[idx] * HDIM + col;
        float4 v;
        v = *(const float4*)(h1 + b); a1.x += v.x; a1.y += v.y; a1.z += v.z; a1.w += v.w;
        v = *(const float4*)(c1 + b); a2.x += v.x; a2.y += v.y; a2.z += v.z; a2.w += v.w;
        v = *(const float4*)(h2 + b); a3.x += v.x; a3.y += v.y; a3.z += v.z; a3.w += v.w;
        v = *(const float4*)(c2 + b); a4.x += v.x; a4.y += v.y; a4.z += v.z; a4.w += v.w;
    }

    int ob = node * HDIM + col;
    *(float4*)(g_mh1 + ob) = a1;
    *(float4*)(g_mc1 + ob) = a2;
    *(float4*)(g_mh2 + ob) = a3;
    *(float4*)(g_mc2 + ob) = a4;
}

// ---------------- prep: weights -> [n=512][k=256] (B^T), tf32-rounded ----------------
__global__ void prep_kernel(const float* __restrict__ W1, const float* __restrict__ U1,
                            const float* __restrict__ W2, const float* __restrict__ U2)
{
    int p = blockIdx.y;
    int i = blockIdx.x * 256 + threadIdx.x;   // 131072 per phase
    int k = i >> 9, n = i & 511;
    const float* W = p ? W2 : W1;
    const float* U = p ? U2 : U1;
    float v = (k < 128) ? W[k * 512 + n] : U[(k - 128) * 512 + n];
    g_Bt[p * 131072 + n * 256 + k] = f2tf32(v);
}

// ---------------- fused HMMA(tf32) GEMM + gates ----------------
// Block: 128 rows x 128 cols (cols c = gate g*32 + hh, h = h0+hh), K=256, BK=32.
// 8 warps; warp w -> rows [ (w&1)*64, +64 ), cols [ (w>>1)*32, +32 ).
#define S_A0 0
#define S_A1 16384
#define S_B0 32768
#define S_B1 49152
#define ES_STRIDE 132
#define SMEM_TOTAL (128 * ES_STRIDE * 4)   // 67584 > 65536 mainloop usage

__global__ __launch_bounds__(256, 1)
void lstm_mma_kernel(const float* __restrict__ A1,
                     const float* __restrict__ bW, const float* __restrict__ bU,
                     float* __restrict__ h_out, float* __restrict__ c_out,
                     int nrows, int phase)
{
    extern __shared__ char smem[];
    const uint32_t sbase = smem_u32(smem);
    uint32_t* Sf = (uint32_t*)smem;
    const int tid = threadIdx.x;
    const int h0   = blockIdx.x * 32;
    const int row0 = blockIdx.y * 128;

    const float* A2 = phase ? g_mh2 : g_mh1;
    const float* mc = phase ? g_mc2 : g_mc1;
    const uint32_t* Bt = g_Bt + phase * 131072;

    const int r_st = tid >> 3;        // staging row/col 0..127 (with +0: idx<1024 pattern)
    const int q_st = tid & 7;

    // ---- stage issue: chunk j into buffer b ----
    auto stage = [&](int j, int b) {
        const int k0 = j * 32;
        const float* Ap;
        int kcol;
        if (k0 < 128) { Ap = A1; kcol = k0; }
        else          { Ap = A2; kcol = k0 - 128; }
        uint32_t abase = sbase + (b ? S_A1 : S_A0);
        uint32_t bbase = sbase + (b ? S_B1 : S_B0);
#pragma unroll
        for (int i = 0; i < 4; ++i) {
            int idx = tid + i * 256;
            int r = idx >> 3, q = idx & 7;
            // A: row0+r, cols kcol+q*4
            int gr = row0 + r;
            int ok = (gr < nrows) ? 16 : 0;
            if (gr >= nrows) gr = nrows - 1;
            const float* src = Ap + (size_t)gr * HDIM + kcol + q * 4;
            uint32_t dst = abase + (uint32_t)(r * 32 + ((q ^ (r & 7)) << 2)) * 4;
            cp_async16(dst, src, ok);
            // B: col c=r -> n = g*128 + h0 + hh
            int g = r >> 5, hh = r & 31;
            const uint32_t* bsrc = Bt + (size_t)(g * 128 + h0 + hh) * 256 + k0 + q * 4;
            uint32_t bdst = bbase + (uint32_t)(r * 32 + ((q ^ (r & 7)) << 2)) * 4;
            cp_async16(bdst, bsrc, 16);
        }
        cp_commit();
    };

    const int lane = tid & 31;
    const int warp = tid >> 5;
    const int wm = warp & 1;          // 0/1 -> row half
    const int wn = warp >> 1;         // 0..3 -> col quadrant
    const int g8  = lane >> 2;        // groupID
    const int tig = lane & 3;

    float acc[4][4][4];
#pragma unroll
    for (int a = 0; a < 4; ++a)
#pragma unroll
        for (int b = 0; b < 4; ++b)
#pragma unroll
            for (int c = 0; c < 4; ++c) acc[a][b][c] = 0.f;

    stage(0, 0);

    for (int j = 0; j < 8; ++j) {
        const int buf = j & 1;
        if (j < 7) { stage(j + 1, buf ^ 1); cp_wait1(); }
        else       { cp_wait0(); }
        __syncthreads();

        const uint32_t* As = Sf + (buf ? S_A1 / 4 : S_A0 / 4);
        const uint32_t* Bs = Sf + (buf ? S_B1 / 4 : S_B0 / 4);

#pragma unroll
        for (int ks = 0; ks < 4; ++ks) {
            uint32_t af[4][4], bf[4][2];
            const int kk = ks * 8 + tig;
#pragma unroll
            for (int mt = 0; mt < 4; ++mt) {
                int r = wm * 64 + mt * 16 + g8;
                af[mt][0] = As[soff(r,     kk)];
                af[mt][1] = As[soff(r + 8, kk)];
                af[mt][2] = As[soff(r,     kk + 4)];
                af[mt][3] = As[soff(r + 8, kk + 4)];
            }
#pragma unroll
            for (int nt = 0; nt < 4; ++nt) {
                int c = wn * 32 + nt * 8 + g8;
                bf[nt][0] = Bs[soff(c, kk)];
                bf[nt][1] = Bs[soff(c, kk + 4)];
            }
#pragma unroll
            for (int mt = 0; mt < 4; ++mt)
#pragma unroll
                for (int nt = 0; nt < 4; ++nt)
                    mma_tf32(acc[mt][nt], af[mt][0], af[mt][1], af[mt][2], af[mt][3],
                             bf[nt][0], bf[nt][1]);
        }
        __syncthreads();
    }

    // ---- park accumulators in smem (Es[128][132]) ----
    float* Es = (float*)smem;
#pragma unroll
    for (int mt = 0; mt < 4; ++mt) {
#pragma unroll
        for (int nt = 0; nt < 4; ++nt) {
            int r = wm * 64 + mt * 16 + g8;
            int c = wn * 32 + nt * 8 + 2 * tig;
            *(float2*)(Es + r * ES_STRIDE + c)       = make_float2(acc[mt][nt][0], acc[mt][nt][1]);
            *(float2*)(Es + (r + 8) * ES_STRIDE + c) = make_float2(acc[mt][nt][2], acc[mt][nt][3]);
        }
    }
    __syncthreads();

    // ---- gate pass: thread -> hh = tid&31, rows (tid>>5) + 8*it ----
    {
        const int hh = tid & 31;
        const int rbase = tid >> 5;
        const int h = h0 + hh;
        const float bi = bW[h]       + bU[h];
        const float bo = bW[128 + h] + bU[128 + h];
        const float bu = bW[256 + h] + bU[256 + h];
        const float bfm = bW[384 + h] + bU[384 + h];
#pragma unroll 4
        for (int it = 0; it < 16; ++it) {
            int r = rbase + it * 8;
            int grow = row0 + r;
            if (grow >= nrows) continue;
            float xi = Es[r * ES_STRIDE + hh]      + bi;
            float xo = Es[r * ES_STRIDE + 32 + hh] + bo;
            float xu = Es[r * ES_STRIDE + 64 + hh] + bu;
            float xf = Es[r * ES_STRIDE + 96 + hh] + bfm;
            float gi = 1.f / (1.f + __expf(-xi));
            float go = 1.f / (1.f + __expf(-xo));
            float gu = tanhf(xu);
            float gf = 1.f / (1.f + __expf(-xf));
            float mcv = mc[(size_t)grow * HDIM + h];
            float cn = gi * gu + gf * mcv;
            float hn = go * tanhf(cn);
            c_out[(size_t)grow * HDIM + h] = cn;
            h_out[(size_t)grow * HDIM + h] = hn;
        }
    }
}

// ---------------- host ----------------
extern "C" void kernel_launch(void* const* d_in, const int* in_sizes, int n_in,
                              void* d_out, int out_size)
{
    const float* x   = (const float*)d_in[0];
    const float* h1  = (const float*)d_in[1];
    const float* c1  = (const float*)d_in[2];
    const float* h2  = (const float*)d_in[3];
    const float* c2  = (const float*)d_in[4];
    const float* W1  = (const float*)d_in[5];
    const float* bW1 = (const float*)d_in[6];
    const float* U1  = (const float*)d_in[7];
    const float* bU1 = (const float*)d_in[8];
    const float* W2  = (const float*)d_in[9];
    const float* bW2 = (const float*)d_in[10];
    const float* U2  = (const float*)d_in[11];
    const float* bU2 = (const float*)d_in[12];
    const int*   src = (const int*)d_in[13];
    const int*   dst = (const int*)d_in[14];

    int n = in_sizes[1] / HDIM;
    int e = in_sizes[13];

    float* out = (float*)d_out;
    float* h1n = out;
    float* c1n = out + (size_t)n * HDIM;
    float* h2n = out + 2 * (size_t)n * HDIM;
    float* c2n = out + 3 * (size_t)n * HDIM;

    static int smem_set = 0;
    if (!smem_set) {
        cudaFuncSetAttribute(lstm_mma_kernel,
                             cudaFuncAttributeMaxDynamicSharedMemorySize, SMEM_TOTAL);
        smem_set = 1;
    }

    {
        dim3 grid(512, 2);
        prep_kernel<<<grid, 256>>>(W1, U1, W2, U2);
    }
    {
        int blocks = (n + 7) / 8;
        gather_kernel<<<blocks, 256>>>(h1, c1, h2, c2, src, dst, n, e);
    }
    int mtiles = (n + 127) / 128;
    dim3 grid(4, mtiles);
    lstm_mma_kernel<<<grid, 256, SMEM_TOTAL>>>(x, bW1, bU1, h1n, c1n, n, 0);
    lstm_mma_kernel<<<grid, 256, SMEM_TOTAL>>>(c1n, bW2, bU2, h2n, c2n, n, 1);
}

// round 4
// speedup vs baseline: 2.2341x; 1.4530x over previous
#include <cuda_runtime.h>
#include <cstdint>
#include <math.h>

#define HDIM 128
#define MAXN 200000

// ---------------- device scratch ----------------
__device__ float g_mh1[MAXN * HDIM];
__device__ float g_mc1[MAXN * HDIM];
__device__ float g_mh2[MAXN * HDIM];
__device__ float g_mc2[MAXN * HDIM];
// transposed + tf32-rounded weights: [phase][n=512][k=256]
__device__ uint32_t g_Bt[2 * 512 * 256];

__device__ __forceinline__ uint32_t smem_u32(const void* p) {
    uint32_t a;
    asm("{ .reg .u64 t; cvta.to.shared.u64 t, %1; cvt.u32.u64 %0, t; }" : "=r"(a) : "l"(p));
    return a;
}
__device__ __forceinline__ uint32_t f2tf32(float f) {
    uint32_t o;
    asm("cvt.rna.tf32.f32 %0, %1;" : "=r"(o) : "f"(f));
    return o;
}
__device__ __forceinline__ void cp_async16(uint32_t dst, const void* src, int src_bytes) {
    asm volatile("cp.async.cg.shared.global [%0], [%1], 16, %2;"
                 :: "r"(dst), "l"(src), "r"(src_bytes) : "memory");
}
__device__ __forceinline__ void cp_commit() {
    asm volatile("cp.async.commit_group;" ::: "memory");
}
__device__ __forceinline__ void cp_wait1() {
    asm volatile("cp.async.wait_group 1;" ::: "memory");
}
__device__ __forceinline__ void cp_wait0() {
    asm volatile("cp.async.wait_group 0;" ::: "memory");
}
__device__ __forceinline__ void mma_tf32(float* d, uint32_t a0, uint32_t a1, uint32_t a2,
                                         uint32_t a3, uint32_t b0, uint32_t b1) {
    asm volatile(
        "mma.sync.aligned.m16n8k8.row.col.f32.tf32.tf32.f32 "
        "{%0,%1,%2,%3}, {%4,%5,%6,%7}, {%8,%9}, {%0,%1,%2,%3};"
        : "+f"(d[0]), "+f"(d[1]), "+f"(d[2]), "+f"(d[3])
        : "r"(a0), "r"(a1), "r"(a2), "r"(a3), "r"(b0), "r"(b1));
}

// XOR-swizzled smem offset for 128x32-float tiles (float index)
__device__ __forceinline__ int soff(int r, int kk) {
    return r * 32 + (((kk >> 2) ^ (r & 7)) << 2) + (kk & 3);
}

// ---------------- gather: sorted-dst segment sum, 1 warp / node ----------------
__global__ void gather_kernel(const float* __restrict__ h1, const float* __restrict__ c1,
                              const float* __restrict__ h2, const float* __restrict__ c2,
                              const int* __restrict__ src, const int* __restrict__ dst,
                              int n, int e)
{
    int node = (blockIdx.x * blockDim.x + threadIdx.x) >> 5;
    int lane = threadIdx.x & 31;
    if (node >= n) return;

    int lo = 0, hi = e;
    while (lo < hi) { int mid = (lo + hi) >> 1; if (dst[mid] < node) lo = mid + 1; else hi = mid; }
    int s = lo;
    hi = e;
    while (lo < hi) { int mid = (lo + hi) >> 1; if (dst[mid] < node + 1) lo = mid + 1; else hi = mid; }
    int send = lo;

    float4 a1 = make_float4(0.f, 0.f, 0.f, 0.f);
    float4 a2 = a1, a3 = a1, a4 = a1;
    int col = lane * 4;

    for (int idx = s; idx < send; ++idx) {
        int b = src[idx] * HDIM + col;
        float4 v;
        v = *(const float4*)(h1 + b); a1.x += v.x; a1.y += v.y; a1.z += v.z; a1.w += v.w;
        v = *(const float4*)(c1 + b); a2.x += v.x; a2.y += v.y; a2.z += v.z; a2.w += v.w;
        v = *(const float4*)(h2 + b); a3.x += v.x; a3.y += v.y; a3.z += v.z; a3.w += v.w;
        v = *(const float4*)(c2 + b); a4.x += v.x; a4.y += v.y; a4.z += v.z; a4.w += v.w;
    }

    int ob = node * HDIM + col;
    *(float4*)(g_mh1 + ob) = a1;
    *(float4*)(g_mc1 + ob) = a2;
    *(float4*)(g_mh2 + ob) = a3;
    *(float4*)(g_mc2 + ob) = a4;
}

// ---------------- prep: weights -> [n=512][k=256] (B^T), tf32-rounded ----------------
__global__ void prep_kernel(const float* __restrict__ W1, const float* __restrict__ U1,
                            const float* __restrict__ W2, const float* __restrict__ U2)
{
    int p = blockIdx.y;
    int i = blockIdx.x * 256 + threadIdx.x;   // 131072 per phase
    int k = i >> 9, n = i & 511;
    const float* W = p ? W2 : W1;
    const float* U = p ? U2 : U1;
    float v = (k < 128) ? W[k * 512 + n] : U[(k - 128) * 512 + n];
    g_Bt[p * 131072 + n * 256 + k] = f2tf32(v);
}

// ---------------- fused HMMA(tf32) GEMM + gates ----------------
// Block: 128 rows x 128 cols (cols c = gate g*32 + hh, h = h0+hh), K=256, BK=32.
// 8 warps; warp w -> rows [ (w&1)*64, +64 ), cols [ (w>>1)*32, +32 ).
// launch_bounds(256,2): 2 CTAs/SM (regs <= 128) to hide HMMA/LDS latency.
#define S_A0 0
#define S_A1 16384
#define S_B0 32768
#define S_B1 49152
#define ES_STRIDE 132
#define SMEM_TOTAL (128 * ES_STRIDE * 4)   // 67584

__global__ __launch_bounds__(256, 2)
void lstm_mma_kernel(const float* __restrict__ A1,
                     const float* __restrict__ bW, const float* __restrict__ bU,
                     float* __restrict__ h_out, float* __restrict__ c_out,
                     int nrows, int phase)
{
    extern __shared__ char smem[];
    const uint32_t sbase = smem_u32(smem);
    uint32_t* Sf = (uint32_t*)smem;
    const int tid = threadIdx.x;
    const int h0   = blockIdx.x * 32;
    const int row0 = blockIdx.y * 128;

    const float* A2 = phase ? g_mh2 : g_mh1;
    const float* mc = phase ? g_mc2 : g_mc1;
    const uint32_t* Bt = g_Bt + phase * 131072;

    // ---- loop-invariant staging state (register diet) ----
    const int r0 = tid >> 3;               // 0..31
    const int q  = tid & 7;                // column quad
    // swizzle offset identical for all 4 i-strides (low 3 bits of row invariant)
    const uint32_t sw0 = (uint32_t)(r0 * 32 + ((q ^ (r0 & 7)) << 2)) * 4;

    int grc[4];   // A source element offsets (row*128 + q*4), clamped
    int aok[4];   // 16 or 0 (zfill) for OOB rows
    const uint32_t* pB[4];
#pragma unroll
    for (int i = 0; i < 4; ++i) {
        int gr = row0 + r0 + 32 * i;
        aok[i] = (gr < nrows) ? 16 : 0;
        if (gr >= nrows) gr = nrows - 1;
        grc[i] = gr * HDIM + q * 4;
        pB[i] = Bt + (size_t)(i * 128 + h0 + r0) * 256 + q * 4;
    }

    auto stage = [&](int j, int b) {
        const float* Ap = (j < 4) ? A1 : A2;
        const int kcol = (j & 3) * 32;
        const int k0 = j * 32;
        const uint32_t abase = sbase + (b ? S_A1 : S_A0) + sw0;
        const uint32_t bbase = sbase + (b ? S_B1 : S_B0) + sw0;
#pragma unroll
        for (int i = 0; i < 4; ++i) {
            cp_async16(abase + 4096u * i, Ap + grc[i] + kcol, aok[i]);
            cp_async16(bbase + 4096u * i, pB[i] + k0, 16);
        }
        cp_commit();
    };

    const int lane = tid & 31;
    const int warp = tid >> 5;
    const int wm = warp & 1;          // 0/1 -> row half
    const int wn = warp >> 1;         // 0..3 -> col quadrant
    const int g8  = lane >> 2;        // groupID
    const int tig = lane & 3;

    float acc[4][4][4];
#pragma unroll
    for (int a = 0; a < 4; ++a)
#pragma unroll
        for (int b = 0; b < 4; ++b)
#pragma unroll
            for (int c = 0; c < 4; ++c) acc[a][b][c] = 0.f;

    stage(0, 0);

    for (int j = 0; j < 8; ++j) {
        const int buf = j & 1;
        if (j < 7) { stage(j + 1, buf ^ 1); cp_wait1(); }
        else       { cp_wait0(); }
        __syncthreads();

        const uint32_t* As = Sf + (buf ? S_A1 / 4 : S_A0 / 4);
        const uint32_t* Bs = Sf + (buf ? S_B1 / 4 : S_B0 / 4);

#pragma unroll
        for (int ks = 0; ks < 4; ++ks) {
            uint32_t af[4][4], bf[4][2];
            const int kk = ks * 8 + tig;
#pragma unroll
            for (int mt = 0; mt < 4; ++mt) {
                int r = wm * 64 + mt * 16 + g8;
                af[mt][0] = As[soff(r,     kk)];
                af[mt][1] = As[soff(r + 8, kk)];
                af[mt][2] = As[soff(r,     kk + 4)];
                af[mt][3] = As[soff(r + 8, kk + 4)];
            }
#pragma unroll
            for (int nt = 0; nt < 4; ++nt) {
                int c = wn * 32 + nt * 8 + g8;
                bf[nt][0] = Bs[soff(c, kk)];
                bf[nt][1] = Bs[soff(c, kk + 4)];
            }
#pragma unroll
            for (int mt = 0; mt < 4; ++mt)
#pragma unroll
                for (int nt = 0; nt < 4; ++nt)
                    mma_tf32(acc[mt][nt], af[mt][0], af[mt][1], af[mt][2], af[mt][3],
                             bf[nt][0], bf[nt][1]);
        }
        __syncthreads();
    }

    // ---- park accumulators in smem (Es[128][132]) ----
    float* Es = (float*)smem;
#pragma unroll
    for (int mt = 0; mt < 4; ++mt) {
#pragma unroll
        for (int nt = 0; nt < 4; ++nt) {
            int r = wm * 64 + mt * 16 + g8;
            int c = wn * 32 + nt * 8 + 2 * tig;
            *(float2*)(Es + r * ES_STRIDE + c)       = make_float2(acc[mt][nt][0], acc[mt][nt][1]);
            *(float2*)(Es + (r + 8) * ES_STRIDE + c) = make_float2(acc[mt][nt][2], acc[mt][nt][3]);
        }
    }
    __syncthreads();

    // ---- gate pass: thread -> hh = tid&31, rows (tid>>5) + 8*it ----
    {
        const int hh = tid & 31;
        const int rbase = tid >> 5;
        const int h = h0 + hh;
        const float bi = bW[h]       + bU[h];
        const float bo = bW[128 + h] + bU[128 + h];
        const float bu = bW[256 + h] + bU[256 + h];
        const float bfm = bW[384 + h] + bU[384 + h];
#pragma unroll 4
        for (int it = 0; it < 16; ++it) {
            int r = rbase + it * 8;
            int grow = row0 + r;
            if (grow >= nrows) continue;
            float xi = Es[r * ES_STRIDE + hh]      + bi;
            float xo = Es[r * ES_STRIDE + 32 + hh] + bo;
            float xu = Es[r * ES_STRIDE + 64 + hh] + bu;
            float xf = Es[r * ES_STRIDE + 96 + hh] + bfm;
            float gi = 1.f / (1.f + __expf(-xi));
            float go = 1.f / (1.f + __expf(-xo));
            float gu = tanhf(xu);
            float gf = 1.f / (1.f + __expf(-xf));
            float mcv = mc[(size_t)grow * HDIM + h];
            float cn = gi * gu + gf * mcv;
            float hn = go * tanhf(cn);
            c_out[(size_t)grow * HDIM + h] = cn;
            h_out[(size_t)grow * HDIM + h] = hn;
        }
    }
}

// ---------------- host ----------------
extern "C" void kernel_launch(void* const* d_in, const int* in_sizes, int n_in,
                              void* d_out, int out_size)
{
    const float* x   = (const float*)d_in[0];
    const float* h1  = (const float*)d_in[1];
    const float* c1  = (const float*)d_in[2];
    const float* h2  = (const float*)d_in[3];
    const float* c2  = (const float*)d_in[4];
    const float* W1  = (const float*)d_in[5];
    const float* bW1 = (const float*)d_in[6];
    const float* U1  = (const float*)d_in[7];
    const float* bU1 = (const float*)d_in[8];
    const float* W2  = (const float*)d_in[9];
    const float* bW2 = (const float*)d_in[10];
    const float* U2  = (const float*)d_in[11];
    const float* bU2 = (const float*)d_in[12];
    const int*   src = (const int*)d_in[13];
    const int*   dst = (const int*)d_in[14];

    int n = in_sizes[1] / HDIM;
    int e = in_sizes[13];

    float* out = (float*)d_out;
    float* h1n = out;
    float* c1n = out + (size_t)n * HDIM;
    float* h2n = out + 2 * (size_t)n * HDIM;
    float* c2n = out + 3 * (size_t)n * HDIM;

    static int smem_set = 0;
    if (!smem_set) {
        cudaFuncSetAttribute(lstm_mma_kernel,
                             cudaFuncAttributeMaxDynamicSharedMemorySize, SMEM_TOTAL);
        smem_set = 1;
    }

    {
        dim3 grid(512, 2);
        prep_kernel<<<grid, 256>>>(W1, U1, W2, U2);
    }
    {
        int blocks = (n + 7) / 8;
        gather_kernel<<<blocks, 256>>>(h1, c1, h2, c2, src, dst, n, e);
    }
    int mtiles = (n + 127) / 128;
    dim3 grid(4, mtiles);
    lstm_mma_kernel<<<grid, 256, SMEM_TOTAL>>>(x, bW1, bU1, h1n, c1n, n, 0);
    lstm_mma_kernel<<<grid, 256, SMEM_TOTAL>>>(c1n, bW2, bU2, h2n, c2n, n, 1);
}